// round 3
// baseline (speedup 1.0000x reference)
#include <cuda_runtime.h>

#define CCH    256
#define NIMG   2
#define NBINS  49
#define NWARP  8
#define WCAP   1216   // per-warp window capacity (floats); proven max area = 1196

// ---------------------------------------------------------------------------
// Direct-from-NCHW ROIAlign FPN pooler. One CTA per box, 8 warps.
// Warp w handles channels [w*32, w*32+32). For each channel it gathers the
// box's bilinear-tap window (contiguous rows along W -> coalesced LDG) into
// its private smem buffer, then each lane computes output bins lane and
// lane+32 from smem and writes them to out[m][c][bin] (contiguous 49 floats).
// Sample indices are stored window-local; invalid samples (outside [-1,size])
// have both bilinear weights zeroed, matching torchvision/ref semantics.
// ---------------------------------------------------------------------------
__global__ __launch_bounds__(256) void roi_pool_direct(
    const float* __restrict__ f0, const float* __restrict__ f1,
    const float* __restrict__ f2, const float* __restrict__ f3,
    const float* __restrict__ boxes, float* __restrict__ out, int R)
{
    __shared__ float s_win[NWARP][WCAP];            // 38,912 B
    __shared__ float s_l[2][14], s_h[2][14];        // bilinear weights (lo, hi)
    __shared__ int   s_t0[2][14], s_t1[2][14];      // window-local tap indices
    __shared__ int   s_dim[2];                      // [0]=ww, [1]=wh
    __shared__ int   s_org[2];                      // [0]=wx0, [1]=wy0

    const int m   = blockIdx.x;
    const int tid = threadIdx.x;

    const float bx1 = __ldg(boxes + 4 * m + 0);
    const float by1 = __ldg(boxes + 4 * m + 1);
    const float bx2 = __ldg(boxes + 4 * m + 2);
    const float by2 = __ldg(boxes + 4 * m + 3);

    // assign_boxes_to_levels
    const float area_b = fmaxf((bx2 - bx1) * (by2 - by1), 0.0f);
    const float sz     = sqrtf(area_b);
    int lvl = (int)floorf(4.0f + log2f(sz / 224.0f + 1e-8f));
    lvl = min(max(lvl, 2), 5) - 2;                  // 0..3

    const int   Hd    = 256 >> lvl;                 // square maps
    const float scale = 0.25f / (float)(1 << lvl);
    const int   n     = m / R;

    const float* feat = (lvl == 0) ? f0 : (lvl == 1) ? f1 : (lvl == 2) ? f2 : f3;

    // 28 threads: 14 x-samples (axis 0) + 14 y-samples (axis 1).
    // Samples are monotone in k (bin size >= 0), so sample 0's i0 is the
    // window origin and sample 13's i1 is the window far edge.
    if (tid < 28) {
        const int axis = tid / 14;
        const int k    = tid - axis * 14;
        const float c1 = axis ? by1 : bx1;
        const float c2 = axis ? by2 : bx2;
        const int  lim = Hd;
        const float start = c1 * scale - 0.5f;
        const float bsz   = (c2 * scale - 0.5f - start) * (1.0f / 7.0f);
        const float off   = (float)(k >> 1) + ((k & 1) ? 0.75f : 0.25f);
        const float t     = start + off * bsz;
        const bool  v     = (t >= -1.0f) && (t <= (float)lim);
        const float tc    = fminf(fmaxf(t, 0.0f), (float)(lim - 1));
        const int   i0    = (int)tc;                // tc >= 0 -> trunc == floor
        const int   i1    = min(i0 + 1, lim - 1);
        const float l     = tc - (float)i0;
        // window origin from sample 0 (every thread recomputes; cheap)
        const float t0  = start + 0.25f * bsz;
        const float tc0 = fminf(fmaxf(t0, 0.0f), (float)(lim - 1));
        const int   o   = (int)tc0;
        s_t0[axis][k] = i0 - o;
        s_t1[axis][k] = i1 - o;
        s_l[axis][k]  = v ? l : 0.0f;
        s_h[axis][k]  = v ? (1.0f - l) : 0.0f;
        if (k == 13) {
            s_dim[axis] = i1 - o + 1;
            s_org[axis] = o;
        }
    }
    __syncthreads();

    const int ww   = s_dim[0];
    const int wh   = s_dim[1];
    const int wx0  = s_org[0];
    const int wy0  = s_org[1];
    int warea = ww * wh;
    if (warea > WCAP) warea = WCAP;                 // defensive (cannot trigger)

    const int w    = tid >> 5;
    const int lane = tid & 31;
    float* win = s_win[w];

    const size_t HW = (size_t)Hd * Hd;
    const float* src0 = feat + ((size_t)n * CCH + w * 32) * HW
                             + (size_t)wy0 * Hd + wx0;
    float* outm = out + (size_t)m * (NBINS * CCH) + (w * 32) * NBINS;

    // bin assignments for this lane
    const int b0  = lane;                           // always < 49
    const int py0 = b0 / 7,  px0 = b0 - py0 * 7;
    const int b1  = lane + 32;
    const int py1 = b1 / 7,  px1 = b1 - py1 * 7;    // only used if b1 < 49

    for (int i = 0; i < 32; ++i) {
        const float* src = src0 + (size_t)i * HW;

        // gather window: flattened, coalesced along rows
        #pragma unroll 2
        for (int idx = lane; idx < warea; idx += 32) {
            const int r   = idx / ww;
            const int col = idx - r * ww;
            win[idx] = __ldg(src + (size_t)r * Hd + col);
        }
        __syncwarp();

        // bin b0
        float acc0 = 0.0f;
        #pragma unroll
        for (int sy = 0; sy < 2; ++sy) {
            const int   iy = py0 * 2 + sy;
            const int   r0 = s_t0[1][iy] * ww;
            const int   r1 = s_t1[1][iy] * ww;
            const float hy = s_h[1][iy], ly = s_l[1][iy];
            #pragma unroll
            for (int sx = 0; sx < 2; ++sx) {
                const int   ix = px0 * 2 + sx;
                const int   x0 = s_t0[0][ix], x1 = s_t1[0][ix];
                const float hx = s_h[0][ix],  lx = s_l[0][ix];
                acc0 += hy * (hx * win[r0 + x0] + lx * win[r0 + x1])
                      + ly * (hx * win[r1 + x0] + lx * win[r1 + x1]);
            }
        }
        outm[i * NBINS + b0] = acc0 * 0.25f;

        // bin b1 (17 lanes)
        if (b1 < NBINS) {
            float acc1 = 0.0f;
            #pragma unroll
            for (int sy = 0; sy < 2; ++sy) {
                const int   iy = py1 * 2 + sy;
                const int   r0 = s_t0[1][iy] * ww;
                const int   r1 = s_t1[1][iy] * ww;
                const float hy = s_h[1][iy], ly = s_l[1][iy];
                #pragma unroll
                for (int sx = 0; sx < 2; ++sx) {
                    const int   ix = px1 * 2 + sx;
                    const int   x0 = s_t0[0][ix], x1 = s_t1[0][ix];
                    const float hx = s_h[0][ix],  lx = s_l[0][ix];
                    acc1 += hy * (hx * win[r0 + x0] + lx * win[r0 + x1])
                          + ly * (hx * win[r1 + x0] + lx * win[r1 + x1]);
                }
            }
            outm[i * NBINS + b1] = acc1 * 0.25f;
        }
        __syncwarp();                               // window reuse barrier
    }
}

// ---------------------------------------------------------------------------
extern "C" void kernel_launch(void* const* d_in, const int* in_sizes, int n_in,
                              void* d_out, int out_size)
{
    const float* f0    = (const float*)d_in[0];
    const float* f1    = (const float*)d_in[1];
    const float* f2    = (const float*)d_in[2];
    const float* f3    = (const float*)d_in[3];
    const float* boxes = (const float*)d_in[4];
    float*       out   = (float*)d_out;

    const int M = in_sizes[4] / 4;   // 1024 boxes
    const int R = M / NIMG;          // 512 per image

    roi_pool_direct<<<M, 256>>>(f0, f1, f2, f3, boxes, out, R);
}

// round 4
// speedup vs baseline: 3.0045x; 3.0045x over previous
#include <cuda_runtime.h>

#define CCH 256        // channels (all levels)
#define NIMG 2         // batch
#define NBINS 49       // 7*7
#define SPITCH 260     // staging pitch in floats (CCH+4): 16B-aligned
#define SPITCH4 65     // pitch in float4

// NHWC scratch for all 4 levels (float):
// L0: 2*256*256*256 = 33,554,432  @ 0
// L1: 2*128*128*256 =  8,388,608  @ 33,554,432
// L2: 2* 64* 64*256 =  2,097,152  @ 41,943,040
// L3: 2* 32* 32*256 =    524,288  @ 44,040,192
__device__ float g_nhwc[44564480];

__constant__ long long c_lvl_off[4] = {0LL, 33554432LL, 41943040LL, 44040192LL};

// ---------------------------------------------------------------------------
// Fused NCHW->NHWC transpose for all 4 levels in ONE launch.
// blockIdx.x segments: L0 tiles [0,2048), L1 [2048,2560), L2 [2560,2688),
// L3 [2688,2720). blockIdx.y = channel tile (8), blockIdx.z = image (2).
// Block (8,32): float4 LDG along HW, float4 STG along C. 32x32 tile.
// ---------------------------------------------------------------------------
__global__ __launch_bounds__(256) void transpose_fused(
    const float* __restrict__ f0, const float* __restrict__ f1,
    const float* __restrict__ f2, const float* __restrict__ f3)
{
    __shared__ float tile[32][33];

    const int bx = blockIdx.x;
    int lvl, t;
    const float* src;
    if (bx < 2048)      { lvl = 0; t = bx;        src = f0; }
    else if (bx < 2560) { lvl = 1; t = bx - 2048; src = f1; }
    else if (bx < 2688) { lvl = 2; t = bx - 2560; src = f2; }
    else                { lvl = 3; t = bx - 2688; src = f3; }

    const int HW  = (256 >> lvl) * (256 >> lvl);
    const int hw0 = t * 32;
    const int c0  = blockIdx.y * 32;
    const int n   = blockIdx.z;
    const int tx  = threadIdx.x;   // 0..7
    const int ty  = threadIdx.y;   // 0..31

    const float* s = src + (size_t)n * CCH * HW;
    float* dst = g_nhwc + c_lvl_off[lvl] + (size_t)n * HW * CCH;

    // load: float4 along HW; tile[c][hw]
    {
        const float4 v = *reinterpret_cast<const float4*>(
            s + (size_t)(c0 + ty) * HW + hw0 + tx * 4);
        tile[ty][tx * 4 + 0] = v.x;
        tile[ty][tx * 4 + 1] = v.y;
        tile[ty][tx * 4 + 2] = v.z;
        tile[ty][tx * 4 + 3] = v.w;
    }
    __syncthreads();

    // store: float4 along C (4 scalar LDS, conflict-free: (4tx+j+ty) mod 32 distinct)
    {
        float4 v;
        v.x = tile[tx * 4 + 0][ty];
        v.y = tile[tx * 4 + 1][ty];
        v.z = tile[tx * 4 + 2][ty];
        v.w = tile[tx * 4 + 3][ty];
        *reinterpret_cast<float4*>(dst + (size_t)(hw0 + ty) * CCH + c0 + tx * 4) = v;
    }
}

// ---------------------------------------------------------------------------
// ROIAlign pooler over NHWC scratch. One CTA per box. 256 threads:
//   q  = tid & 63  -> channel quad (float4), coalesced across warp pair
//   bs = tid >> 6  -> bin set (4 sets strided over the phase's bins)
// Output staged in smem [bin][channel] (two phases of 25/24 bins), then dumped
// transposed to out[m][c][bin] with compile-time phase sizes (no runtime div).
// ---------------------------------------------------------------------------
__device__ __forceinline__ void pool_phase_compute(
    const float4* __restrict__ base4, float4* __restrict__ s4,
    const int (&i0)[2][14], const int (&i1)[2][14],
    const float (&wh)[2][14], const float (&wl)[2][14],
    int Wd, int q, int bs, int b0, int bcnt)
{
    for (int bb = bs; bb < bcnt; bb += 4) {
        const int bin = b0 + bb;
        const int py  = bin / 7;
        const int px  = bin - py * 7;
        float4 acc = make_float4(0.f, 0.f, 0.f, 0.f);
#pragma unroll
        for (int sy = 0; sy < 2; ++sy) {
            const int   iy = py * 2 + sy;
            const int   r0 = i0[1][iy] * Wd;
            const int   r1 = i1[1][iy] * Wd;
            const float hy = wh[1][iy];
            const float ly = wl[1][iy];
#pragma unroll
            for (int sx = 0; sx < 2; ++sx) {
                const int   ix = px * 2 + sx;
                const int   x0 = i0[0][ix];
                const int   x1 = i1[0][ix];
                const float hx = wh[0][ix];
                const float lx = wl[0][ix];
                const float w00 = hy * hx, w01 = hy * lx;
                const float w10 = ly * hx, w11 = ly * lx;
                const float4 v00 = __ldg(base4 + (size_t)(r0 + x0) * 64);
                const float4 v01 = __ldg(base4 + (size_t)(r0 + x1) * 64);
                const float4 v10 = __ldg(base4 + (size_t)(r1 + x0) * 64);
                const float4 v11 = __ldg(base4 + (size_t)(r1 + x1) * 64);
                acc.x += w00 * v00.x + w01 * v01.x + w10 * v10.x + w11 * v11.x;
                acc.y += w00 * v00.y + w01 * v01.y + w10 * v10.y + w11 * v11.y;
                acc.z += w00 * v00.z + w01 * v01.z + w10 * v10.z + w11 * v11.z;
                acc.w += w00 * v00.w + w01 * v01.w + w10 * v10.w + w11 * v11.w;
            }
        }
        acc.x *= 0.25f; acc.y *= 0.25f; acc.z *= 0.25f; acc.w *= 0.25f;
        s4[bb * SPITCH4 + q] = acc;
    }
}

template <int BCNT>
__device__ __forceinline__ void pool_phase_dump(
    const float* __restrict__ s_out, float* __restrict__ outm, int b0, int tid)
{
    // i = c*BCNT + bb; BCNT is compile-time -> magic-multiply div/mod.
    const int cnt = BCNT * CCH;
    for (int i = tid; i < cnt; i += 256) {
        const int c  = i / BCNT;
        const int bb = i - c * BCNT;
        outm[c * NBINS + b0 + bb] = s_out[bb * SPITCH + c];
    }
}

__global__ __launch_bounds__(256) void roi_pool_kernel(
    const float* __restrict__ boxes, float* __restrict__ out, int R)
{
    __shared__ float s_out[25 * SPITCH];           // 26,000 B
    __shared__ int   s_i0[2][14], s_i1[2][14];
    __shared__ float s_h[2][14],  s_l[2][14];

    const int m   = blockIdx.x;
    const int tid = threadIdx.x;

    const float bx1 = __ldg(boxes + 4 * m + 0);
    const float by1 = __ldg(boxes + 4 * m + 1);
    const float bx2 = __ldg(boxes + 4 * m + 2);
    const float by2 = __ldg(boxes + 4 * m + 3);

    const float area = fmaxf((bx2 - bx1) * (by2 - by1), 0.0f);
    const float sz   = sqrtf(area);
    int lvl = (int)floorf(4.0f + log2f(sz / 224.0f + 1e-8f));
    lvl = min(max(lvl, 2), 5) - 2;                 // 0..3

    const int   Hd    = 256 >> lvl;
    const int   Wd    = Hd;
    const float scale = 0.25f / (float)(1 << lvl);
    const int   n     = m / R;

    const float* fbase = g_nhwc + c_lvl_off[lvl] + (size_t)n * Hd * Wd * CCH;

    if (tid < 28) {
        const int axis = tid / 14;                 // 0 = x, 1 = y
        const int k    = tid - axis * 14;
        const float c1 = axis ? by1 : bx1;
        const float c2 = axis ? by2 : bx2;
        const int  lim = Hd;
        const float start = c1 * scale - 0.5f;
        const float bsz   = (c2 * scale - 0.5f - start) * (1.0f / 7.0f);
        const float off   = (float)(k >> 1) + ((k & 1) ? 0.75f : 0.25f);
        const float t     = start + off * bsz;
        const bool  v     = (t >= -1.0f) && (t <= (float)lim);
        const float tc    = fminf(fmaxf(t, 0.0f), (float)(lim - 1));
        const int   i0    = (int)tc;
        const int   i1    = min(i0 + 1, lim - 1);
        const float l     = tc - (float)i0;
        s_i0[axis][k] = i0;
        s_i1[axis][k] = i1;
        s_l[axis][k]  = v ? l : 0.0f;
        s_h[axis][k]  = v ? (1.0f - l) : 0.0f;
    }
    __syncthreads();

    const int q  = tid & 63;
    const int bs = tid >> 6;
    const float4* base4 = reinterpret_cast<const float4*>(fbase) + q;
    float4* s4  = reinterpret_cast<float4*>(s_out);
    float* outm = out + (size_t)m * (NBINS * CCH);

    // phase 0: bins [0,25)
    pool_phase_compute(base4, s4, s_i0, s_i1, s_h, s_l, Wd, q, bs, 0, 25);
    __syncthreads();
    pool_phase_dump<25>(s_out, outm, 0, tid);
    __syncthreads();

    // phase 1: bins [25,49)
    pool_phase_compute(base4, s4, s_i0, s_i1, s_h, s_l, Wd, q, bs, 25, 24);
    __syncthreads();
    pool_phase_dump<24>(s_out, outm, 25, tid);
}

// ---------------------------------------------------------------------------
extern "C" void kernel_launch(void* const* d_in, const int* in_sizes, int n_in,
                              void* d_out, int out_size)
{
    const float* f0    = (const float*)d_in[0];
    const float* f1    = (const float*)d_in[1];
    const float* f2    = (const float*)d_in[2];
    const float* f3    = (const float*)d_in[3];
    const float* boxes = (const float*)d_in[4];
    float*       out   = (float*)d_out;

    const int M = in_sizes[4] / 4;   // 1024 boxes
    const int R = M / NIMG;          // 512 per image

    transpose_fused<<<dim3(2720, CCH / 32, NIMG), dim3(8, 32)>>>(f0, f1, f2, f3);
    roi_pool_kernel<<<M, 256>>>(boxes, out, R);
}